// round 1
// baseline (speedup 1.0000x reference)
#include <cuda_runtime.h>
#include <math.h>

#define NMAX 100000
#define EMAX 3200000
#define F_IN 128
#define HID  16
#define NC   10
#define CP   12   // NC padded to 12 floats (48B) so rows are float4-aligned

// ---- scratch (no allocation allowed; static device globals) ----
__device__ float g_g1 [NMAX * HID];   // (x@W1) * dinv
__device__ float g_tmp1[NMAX * HID];  // scatter accumulator layer 1
__device__ float g_g2 [NMAX * CP];    // (h@W2) * dinv, padded
__device__ float g_tmp2[NMAX * CP];   // scatter accumulator layer 2
__device__ float g_dinv[NMAX];
__device__ float g_deg [NMAX];

// ---------------------------------------------------------------
__global__ void zero_kernel(int n) {
    int i = blockIdx.x * blockDim.x + threadIdx.x;
    int n1 = n * HID;
    int n2 = n1 + n * CP;
    int n3 = n2 + n;
    if (i < n1)       g_tmp1[i] = 0.f;
    else if (i < n2)  g_tmp2[i - n1] = 0.f;
    else if (i < n3)  g_deg[i - n2] = 0.f;
}

__global__ void deg_kernel(const int* __restrict__ dst, int e) {
    int i = blockIdx.x * blockDim.x + threadIdx.x;
    if (i < e) atomicAdd(&g_deg[dst[i]], 1.0f);
}

__global__ void dinv_kernel(int n) {
    int i = blockIdx.x * blockDim.x + threadIdx.x;
    if (i < n) g_dinv[i] = rsqrtf(g_deg[i] + 1.0f);
}

// ---- GEMM1: g1 = (x @ W1) * dinv.   x:[n,128], W1:[128,16] ----
// 256 threads, 256 rows/block. K staged through smem in 4 chunks of 32.
__global__ __launch_bounds__(256) void gemm1_kernel(const float* __restrict__ x,
                                                    const float* __restrict__ W1,
                                                    int n) {
    __shared__ float xs[256][33];     // pad -> conflict-free row reads
    __shared__ float w1s[512];        // 32 k x 16 o chunk of W1
    const int tid  = threadIdx.x;
    const int row0 = blockIdx.x * 256;

    float acc[16];
#pragma unroll
    for (int o = 0; o < 16; ++o) acc[o] = 0.f;

    for (int kc = 0; kc < 4; ++kc) {
        // cooperative coalesced load of 256x32 chunk
#pragma unroll
        for (int i = tid; i < 256 * 32; i += 256) {
            int r = i >> 5, k = i & 31;
            int row = row0 + r;
            xs[r][k] = (row < n) ? x[row * F_IN + kc * 32 + k] : 0.f;
        }
        w1s[tid]       = W1[kc * 512 + tid];
        w1s[tid + 256] = W1[kc * 512 + tid + 256];
        __syncthreads();

#pragma unroll
        for (int k = 0; k < 32; ++k) {
            float xv = xs[tid][k];
            float4 wa = *(const float4*)&w1s[k * 16 + 0];
            float4 wb = *(const float4*)&w1s[k * 16 + 4];
            float4 wc = *(const float4*)&w1s[k * 16 + 8];
            float4 wd = *(const float4*)&w1s[k * 16 + 12];
            acc[0]  = fmaf(xv, wa.x, acc[0]);  acc[1]  = fmaf(xv, wa.y, acc[1]);
            acc[2]  = fmaf(xv, wa.z, acc[2]);  acc[3]  = fmaf(xv, wa.w, acc[3]);
            acc[4]  = fmaf(xv, wb.x, acc[4]);  acc[5]  = fmaf(xv, wb.y, acc[5]);
            acc[6]  = fmaf(xv, wb.z, acc[6]);  acc[7]  = fmaf(xv, wb.w, acc[7]);
            acc[8]  = fmaf(xv, wc.x, acc[8]);  acc[9]  = fmaf(xv, wc.y, acc[9]);
            acc[10] = fmaf(xv, wc.z, acc[10]); acc[11] = fmaf(xv, wc.w, acc[11]);
            acc[12] = fmaf(xv, wd.x, acc[12]); acc[13] = fmaf(xv, wd.y, acc[13]);
            acc[14] = fmaf(xv, wd.z, acc[14]); acc[15] = fmaf(xv, wd.w, acc[15]);
        }
        __syncthreads();
    }

    int row = row0 + tid;
    if (row < n) {
        float dv = g_dinv[row];
        float* out = g_g1 + row * HID;
#pragma unroll
        for (int o = 0; o < 16; o += 4) {
            float4 v = make_float4(acc[o] * dv, acc[o + 1] * dv,
                                   acc[o + 2] * dv, acc[o + 3] * dv);
            *(float4*)(out + o) = v;
        }
    }
}

__device__ __forceinline__ void red4(float* p, float4 v) {
    asm volatile("red.global.add.v4.f32 [%0], {%1,%2,%3,%4};"
                 :: "l"(p), "f"(v.x), "f"(v.y), "f"(v.z), "f"(v.w) : "memory");
}

// ---- edge scatter layer 1: tmp1[dst] += g1[src], 4 threads/edge ----
__global__ void edge1_kernel(const int* __restrict__ src,
                             const int* __restrict__ dst, int e) {
    int t = blockIdx.x * blockDim.x + threadIdx.x;
    int ei = t >> 2;
    if (ei >= e) return;
    int q = (t & 3) << 2;
    int s = src[ei], d = dst[ei];
    float4 v = *(const float4*)(g_g1 + s * HID + q);
    red4(g_tmp1 + d * HID + q, v);
}

// ---- finalize layer1 + GEMM2 fused: h=relu(dinv*(tmp1+g1)+b1); g2=(h@W2)*dinv ----
__global__ __launch_bounds__(256) void fin1_kernel(const float* __restrict__ b1,
                                                   const float* __restrict__ W2,
                                                   int n) {
    __shared__ float w2s[HID * NC];
    __shared__ float b1s[HID];
    int tid = threadIdx.x;
    if (tid < HID * NC) w2s[tid] = W2[tid];
    if (tid < HID)      b1s[tid] = b1[tid];
    __syncthreads();

    int i = blockIdx.x * 256 + tid;
    if (i >= n) return;
    float dv = g_dinv[i];

    float h[16];
    const float4* tp = (const float4*)(g_tmp1 + i * HID);
    const float4* gp = (const float4*)(g_g1 + i * HID);
#pragma unroll
    for (int o4 = 0; o4 < 4; ++o4) {
        float4 t = tp[o4], g = gp[o4];
        h[o4 * 4 + 0] = fmaxf(fmaf(dv, t.x + g.x, b1s[o4 * 4 + 0]), 0.f);
        h[o4 * 4 + 1] = fmaxf(fmaf(dv, t.y + g.y, b1s[o4 * 4 + 1]), 0.f);
        h[o4 * 4 + 2] = fmaxf(fmaf(dv, t.z + g.z, b1s[o4 * 4 + 2]), 0.f);
        h[o4 * 4 + 3] = fmaxf(fmaf(dv, t.w + g.w, b1s[o4 * 4 + 3]), 0.f);
    }

    float acc[NC];
#pragma unroll
    for (int c = 0; c < NC; ++c) acc[c] = 0.f;
#pragma unroll
    for (int o = 0; o < HID; ++o) {
        float hv = h[o];
#pragma unroll
        for (int c = 0; c < NC; ++c) acc[c] = fmaf(hv, w2s[o * NC + c], acc[c]);
    }

    float* out = g_g2 + i * CP;
    ((float4*)out)[0] = make_float4(acc[0] * dv, acc[1] * dv, acc[2] * dv, acc[3] * dv);
    ((float4*)out)[1] = make_float4(acc[4] * dv, acc[5] * dv, acc[6] * dv, acc[7] * dv);
    ((float4*)out)[2] = make_float4(acc[8] * dv, acc[9] * dv, 0.f, 0.f);
}

// ---- edge scatter layer 2: tmp2[dst] += g2[src], 3 threads/edge (12 padded cols) ----
__global__ void edge2_kernel(const int* __restrict__ src,
                             const int* __restrict__ dst, int e) {
    int t = blockIdx.x * blockDim.x + threadIdx.x;
    int ei = t / 3;
    if (ei >= e) return;
    int q = (t - ei * 3) << 2;
    int s = src[ei], d = dst[ei];
    float4 v = *(const float4*)(g_g2 + s * CP + q);
    red4(g_tmp2 + d * CP + q, v);
}

// ---- finalize layer2 + softmax ----
__global__ __launch_bounds__(256) void fin2_kernel(const float* __restrict__ b2,
                                                   float* __restrict__ out, int n) {
    __shared__ float b2s[NC];
    if (threadIdx.x < NC) b2s[threadIdx.x] = b2[threadIdx.x];
    __syncthreads();
    int i = blockIdx.x * blockDim.x + threadIdx.x;
    if (i >= n) return;
    float dv = g_dinv[i];
    const float* tp = g_tmp2 + i * CP;
    const float* gp = g_g2 + i * CP;
    float l[NC];
    float m = -1e30f;
#pragma unroll
    for (int c = 0; c < NC; ++c) {
        l[c] = fmaf(dv, tp[c] + gp[c], b2s[c]);
        m = fmaxf(m, l[c]);
    }
    float sum = 0.f;
#pragma unroll
    for (int c = 0; c < NC; ++c) {
        l[c] = expf(l[c] - m);
        sum += l[c];
    }
    float inv = 1.0f / sum;
#pragma unroll
    for (int c = 0; c < NC; ++c) out[i * NC + c] = l[c] * inv;
}

// ---------------------------------------------------------------
extern "C" void kernel_launch(void* const* d_in, const int* in_sizes, int n_in,
                              void* d_out, int out_size) {
    const float* x  = (const float*)d_in[0];
    const int*   ei = (const int*)  d_in[1];
    const float* W1 = (const float*)d_in[2];
    const float* b1 = (const float*)d_in[3];
    const float* W2 = (const float*)d_in[4];
    const float* b2 = (const float*)d_in[5];
    float* out = (float*)d_out;

    int n = in_sizes[0] / F_IN;
    int e = in_sizes[1] / 2;
    const int* src = ei;
    const int* dst = ei + e;

    int zt = n * (HID + CP + 1);
    zero_kernel<<<(zt + 255) / 256, 256>>>(n);
    deg_kernel <<<(e + 255) / 256, 256>>>(dst, e);
    dinv_kernel<<<(n + 255) / 256, 256>>>(n);
    gemm1_kernel<<<(n + 255) / 256, 256>>>(x, W1, n);
    edge1_kernel<<<(4 * e + 255) / 256, 256>>>(src, dst, e);
    fin1_kernel<<<(n + 255) / 256, 256>>>(b1, W2, n);
    edge2_kernel<<<(3 * e + 255) / 256, 256>>>(src, dst, e);
    fin2_kernel<<<(n + 255) / 256, 256>>>(b2, out, n);
}

// round 2
// speedup vs baseline: 1.0774x; 1.0774x over previous
#include <cuda_runtime.h>
#include <math.h>

#define NMAX 100000
#define EMAX 3200000
#define F_IN 128
#define HID  16
#define NC   10
#define CP   12   // NC padded to 12 floats (48B) so rows are float4-aligned

// ---- scratch (no allocation allowed; static device globals) ----
__device__ float g_g1 [NMAX * HID];   // (x@W1) * dinv
__device__ float g_tmp1[NMAX * HID];  // scatter accumulator layer 1
__device__ float g_g2 [NMAX * CP];    // (h@W2) * dinv, padded
__device__ float g_tmp2[NMAX * CP];   // scatter accumulator layer 2
__device__ float g_dinv[NMAX];
__device__ float g_deg [NMAX];

// ---------------------------------------------------------------
__global__ void zero_kernel(int n) {
    int i = blockIdx.x * blockDim.x + threadIdx.x;
    int n1 = n * HID;
    int n2 = n1 + n * CP;
    int n3 = n2 + n;
    if (i < n1)       g_tmp1[i] = 0.f;
    else if (i < n2)  g_tmp2[i - n1] = 0.f;
    else if (i < n3)  g_deg[i - n2] = 0.f;
}

__global__ void deg_kernel(const int* __restrict__ dst, int e) {
    int i = blockIdx.x * blockDim.x + threadIdx.x;
    if (i < e) atomicAdd(&g_deg[dst[i]], 1.0f);
}

__global__ void dinv_kernel(int n) {
    int i = blockIdx.x * blockDim.x + threadIdx.x;
    if (i < n) g_dinv[i] = rsqrtf(g_deg[i] + 1.0f);
}

// ---- GEMM1: g1 = (x @ W1) * dinv.   x:[n,128], W1:[128,16] ----
// Row-per-thread, x loaded straight to registers as float4 (8 independent
// loads in flight per 32-k chunk), W1 broadcast from smem. No barriers in
// the load path -> high MLP, ~60 regs -> 3-4 blocks/SM.
__global__ __launch_bounds__(256) void gemm1_kernel(const float* __restrict__ x,
                                                    const float* __restrict__ W1,
                                                    int n) {
    __shared__ float w1s[F_IN * HID];   // 8 KB, [k][o]
#pragma unroll
    for (int i = threadIdx.x; i < F_IN * HID; i += 256)
        w1s[i] = W1[i];
    __syncthreads();

    int row = blockIdx.x * 256 + threadIdx.x;
    if (row >= n) return;

    const float4* xr = (const float4*)(x + (size_t)row * F_IN);

    float acc[16];
#pragma unroll
    for (int o = 0; o < 16; ++o) acc[o] = 0.f;

#pragma unroll 1
    for (int kc = 0; kc < 4; ++kc) {
        // 8 independent 16B loads (32 k-values)
        float4 xv[8];
#pragma unroll
        for (int j = 0; j < 8; ++j) xv[j] = xr[kc * 8 + j];

#pragma unroll
        for (int j = 0; j < 8; ++j) {
            const float xs0 = xv[j].x, xs1 = xv[j].y, xs2 = xv[j].z, xs3 = xv[j].w;
            const float* w = w1s + (kc * 32 + j * 4) * HID;
#pragma unroll
            for (int o = 0; o < 16; ++o) {
                float a = acc[o];
                a = fmaf(xs0, w[o],            a);
                a = fmaf(xs1, w[HID + o],      a);
                a = fmaf(xs2, w[2 * HID + o],  a);
                a = fmaf(xs3, w[3 * HID + o],  a);
                acc[o] = a;
            }
        }
    }

    float dv = g_dinv[row];
    float* out = g_g1 + (size_t)row * HID;
#pragma unroll
    for (int o = 0; o < 16; o += 4) {
        *(float4*)(out + o) = make_float4(acc[o] * dv, acc[o + 1] * dv,
                                          acc[o + 2] * dv, acc[o + 3] * dv);
    }
}

__device__ __forceinline__ void red4(float* p, float4 v) {
    asm volatile("red.global.add.v4.f32 [%0], {%1,%2,%3,%4};"
                 :: "l"(p), "f"(v.x), "f"(v.y), "f"(v.z), "f"(v.w) : "memory");
}
__device__ __forceinline__ void red2(float* p, float2 v) {
    asm volatile("red.global.add.v2.f32 [%0], {%1,%2};"
                 :: "l"(p), "f"(v.x), "f"(v.y) : "memory");
}

// ---- edge scatter layer 1: tmp1[dst] += g1[src], 4 threads/edge ----
__global__ void edge1_kernel(const int* __restrict__ src,
                             const int* __restrict__ dst, int e) {
    int t = blockIdx.x * blockDim.x + threadIdx.x;
    int ei = t >> 2;
    if (ei >= e) return;
    int q = (t & 3) << 2;
    int s = src[ei], d = dst[ei];
    float4 v = *(const float4*)(g_g1 + s * HID + q);
    red4(g_tmp1 + d * HID + q, v);
}

// ---- finalize layer1 + GEMM2 fused: h=relu(dinv*(tmp1+g1)+b1); g2=(h@W2)*dinv ----
__global__ __launch_bounds__(256) void fin1_kernel(const float* __restrict__ b1,
                                                   const float* __restrict__ W2,
                                                   int n) {
    __shared__ float w2s[HID * NC];
    __shared__ float b1s[HID];
    int tid = threadIdx.x;
    if (tid < HID * NC) w2s[tid] = W2[tid];
    if (tid < HID)      b1s[tid] = b1[tid];
    __syncthreads();

    int i = blockIdx.x * 256 + tid;
    if (i >= n) return;
    float dv = g_dinv[i];

    float h[16];
    const float4* tp = (const float4*)(g_tmp1 + i * HID);
    const float4* gp = (const float4*)(g_g1 + i * HID);
#pragma unroll
    for (int o4 = 0; o4 < 4; ++o4) {
        float4 t = tp[o4], g = gp[o4];
        h[o4 * 4 + 0] = fmaxf(fmaf(dv, t.x + g.x, b1s[o4 * 4 + 0]), 0.f);
        h[o4 * 4 + 1] = fmaxf(fmaf(dv, t.y + g.y, b1s[o4 * 4 + 1]), 0.f);
        h[o4 * 4 + 2] = fmaxf(fmaf(dv, t.z + g.z, b1s[o4 * 4 + 2]), 0.f);
        h[o4 * 4 + 3] = fmaxf(fmaf(dv, t.w + g.w, b1s[o4 * 4 + 3]), 0.f);
    }

    float acc[NC];
#pragma unroll
    for (int c = 0; c < NC; ++c) acc[c] = 0.f;
#pragma unroll
    for (int o = 0; o < HID; ++o) {
        float hv = h[o];
#pragma unroll
        for (int c = 0; c < NC; ++c) acc[c] = fmaf(hv, w2s[o * NC + c], acc[c]);
    }

    float* out = g_g2 + i * CP;
    ((float4*)out)[0] = make_float4(acc[0] * dv, acc[1] * dv, acc[2] * dv, acc[3] * dv);
    ((float4*)out)[1] = make_float4(acc[4] * dv, acc[5] * dv, acc[6] * dv, acc[7] * dv);
    ((float4*)out)[2] = make_float4(acc[8] * dv, acc[9] * dv, 0.f, 0.f);
}

// ---- edge scatter layer 2: tmp2[dst] += g2[src] (10 real cols):
// 3 threads/edge: r=0,1 -> red4 on cols 0-7; r=2 -> red2 on cols 8-9 ----
__global__ void edge2_kernel(const int* __restrict__ src,
                             const int* __restrict__ dst, int e) {
    int t = blockIdx.x * blockDim.x + threadIdx.x;
    int ei = t / 3;
    if (ei >= e) return;
    int r = t - ei * 3;
    int s = src[ei], d = dst[ei];
    if (r < 2) {
        int q = r << 2;
        float4 v = *(const float4*)(g_g2 + s * CP + q);
        red4(g_tmp2 + d * CP + q, v);
    } else {
        float2 v = *(const float2*)(g_g2 + s * CP + 8);
        red2(g_tmp2 + d * CP + 8, v);
    }
}

// ---- finalize layer2 + softmax ----
__global__ __launch_bounds__(256) void fin2_kernel(const float* __restrict__ b2,
                                                   float* __restrict__ out, int n) {
    __shared__ float b2s[NC];
    if (threadIdx.x < NC) b2s[threadIdx.x] = b2[threadIdx.x];
    __syncthreads();
    int i = blockIdx.x * blockDim.x + threadIdx.x;
    if (i >= n) return;
    float dv = g_dinv[i];
    const float* tp = g_tmp2 + i * CP;
    const float* gp = g_g2 + i * CP;
    float l[NC];
    float m = -1e30f;
#pragma unroll
    for (int c = 0; c < NC; ++c) {
        l[c] = fmaf(dv, tp[c] + gp[c], b2s[c]);
        m = fmaxf(m, l[c]);
    }
    float sum = 0.f;
#pragma unroll
    for (int c = 0; c < NC; ++c) {
        l[c] = expf(l[c] - m);
        sum += l[c];
    }
    float inv = 1.0f / sum;
#pragma unroll
    for (int c = 0; c < NC; ++c) out[i * NC + c] = l[c] * inv;
}

// ---------------------------------------------------------------
extern "C" void kernel_launch(void* const* d_in, const int* in_sizes, int n_in,
                              void* d_out, int out_size) {
    const float* x  = (const float*)d_in[0];
    const int*   ei = (const int*)  d_in[1];
    const float* W1 = (const float*)d_in[2];
    const float* b1 = (const float*)d_in[3];
    const float* W2 = (const float*)d_in[4];
    const float* b2 = (const float*)d_in[5];
    float* out = (float*)d_out;

    int n = in_sizes[0] / F_IN;
    int e = in_sizes[1] / 2;
    const int* src = ei;
    const int* dst = ei + e;

    int zt = n * (HID + CP + 1);
    zero_kernel<<<(zt + 255) / 256, 256>>>(n);
    deg_kernel <<<(e + 255) / 256, 256>>>(dst, e);
    dinv_kernel<<<(n + 255) / 256, 256>>>(n);
    gemm1_kernel<<<(n + 255) / 256, 256>>>(x, W1, n);
    edge1_kernel<<<(4 * e + 255) / 256, 256>>>(src, dst, e);
    fin1_kernel<<<(n + 255) / 256, 256>>>(b1, W2, n);
    edge2_kernel<<<(3 * e + 255) / 256, 256>>>(src, dst, e);
    fin2_kernel<<<(n + 255) / 256, 256>>>(b2, out, n);
}

// round 5
// speedup vs baseline: 1.1175x; 1.0373x over previous
#include <cuda_runtime.h>
#include <math.h>

#define NMAX 100000
#define EMAX 3200000
#define F_IN 128
#define HID  16
#define NC   10
#define CP   12   // NC padded to 12 floats (48B) so rows are float4-aligned

// ---- scratch (no allocation allowed; static device globals) ----
__device__ float g_g1 [NMAX * HID];   // (x@W1) * dinv
__device__ float g_tmp1[NMAX * HID];  // scatter accumulator layer 1
__device__ float g_g2 [NMAX * CP];    // (h@W2) * dinv, padded
__device__ float g_tmp2[NMAX * CP];   // scatter accumulator layer 2
__device__ float g_dinv[NMAX];
__device__ float g_deg [NMAX];

// ---------------------------------------------------------------
// zero tmp1 (n*16), tmp2 (n*12), deg (n) with float4 stores
__global__ void zero_kernel(int n) {
    int i = blockIdx.x * blockDim.x + threadIdx.x;
    int q1 = n * (HID / 4);            // float4 count of tmp1
    int q2 = q1 + n * (CP / 4);        // + tmp2
    const float4 z = make_float4(0.f, 0.f, 0.f, 0.f);
    if (i < q1)       ((float4*)g_tmp1)[i] = z;
    else if (i < q2)  ((float4*)g_tmp2)[i - q1] = z;
    else if (i < q2 + (n + 3) / 4) {
        int j = (i - q2) * 4;
        #pragma unroll
        for (int k = 0; k < 4; ++k)
            if (j + k < n) g_deg[j + k] = 0.f;
    }
}

__global__ void deg_kernel(const int* __restrict__ dst, int e) {
    int i = blockIdx.x * blockDim.x + threadIdx.x;
    if (i < e) atomicAdd(&g_deg[dst[i]], 1.0f);
}

__global__ void dinv_kernel(int n) {
    int i = blockIdx.x * blockDim.x + threadIdx.x;
    if (i < n) g_dinv[i] = rsqrtf(g_deg[i] + 1.0f);
}

// ---- GEMM1: g1 = (x @ W1) * dinv.   x:[n,128], W1:[128,16] ----
// Warp-staged: each warp owns 32 rows. Per 32-k chunk the warp issues 32
// fully-coalesced 128B row-chunk loads into a padded per-warp smem tile,
// then each lane computes its own row from conflict-free smem.
// No block barriers in the mainloop; only __syncwarp.
__global__ __launch_bounds__(256) void gemm1_kernel(const float* __restrict__ x,
                                                    const float* __restrict__ W1,
                                                    int n) {
    __shared__ float w1s[F_IN * HID];      // 8 KB, [k][o]
    __shared__ float xs[8][32][33];        // per-warp 32 rows x 32 k, padded
#pragma unroll
    for (int i = threadIdx.x; i < F_IN * HID; i += 256)
        w1s[i] = W1[i];
    __syncthreads();

    const int warp = threadIdx.x >> 5;
    const int lane = threadIdx.x & 31;
    const int row0 = blockIdx.x * 256 + warp * 32;
    const int myrow = row0 + lane;

    float acc[16];
#pragma unroll
    for (int o = 0; o < 16; ++o) acc[o] = 0.f;

#pragma unroll 1
    for (int kc = 0; kc < 4; ++kc) {
        // coalesced stage: 32 independent single-line loads (8 in flight)
#pragma unroll 8
        for (int r = 0; r < 32; ++r) {
            int row = row0 + r;
            xs[warp][r][lane] = (row < n)
                ? x[(size_t)row * F_IN + kc * 32 + lane] : 0.f;
        }
        __syncwarp();

#pragma unroll
        for (int k = 0; k < 32; ++k) {
            float xv = xs[warp][lane][k];
            const float* w = w1s + (kc * 32 + k) * HID;
            float4 wa = *(const float4*)(w + 0);
            float4 wb = *(const float4*)(w + 4);
            float4 wc = *(const float4*)(w + 8);
            float4 wd = *(const float4*)(w + 12);
            acc[0]  = fmaf(xv, wa.x, acc[0]);  acc[1]  = fmaf(xv, wa.y, acc[1]);
            acc[2]  = fmaf(xv, wa.z, acc[2]);  acc[3]  = fmaf(xv, wa.w, acc[3]);
            acc[4]  = fmaf(xv, wb.x, acc[4]);  acc[5]  = fmaf(xv, wb.y, acc[5]);
            acc[6]  = fmaf(xv, wb.z, acc[6]);  acc[7]  = fmaf(xv, wb.w, acc[7]);
            acc[8]  = fmaf(xv, wc.x, acc[8]);  acc[9]  = fmaf(xv, wc.y, acc[9]);
            acc[10] = fmaf(xv, wc.z, acc[10]); acc[11] = fmaf(xv, wc.w, acc[11]);
            acc[12] = fmaf(xv, wd.x, acc[12]); acc[13] = fmaf(xv, wd.y, acc[13]);
            acc[14] = fmaf(xv, wd.z, acc[14]); acc[15] = fmaf(xv, wd.w, acc[15]);
        }
        __syncwarp();
    }

    if (myrow < n) {
        float dv = g_dinv[myrow];
        float* out = g_g1 + (size_t)myrow * HID;
#pragma unroll
        for (int o = 0; o < 16; o += 4) {
            *(float4*)(out + o) = make_float4(acc[o] * dv, acc[o + 1] * dv,
                                              acc[o + 2] * dv, acc[o + 3] * dv);
        }
    }
}

__device__ __forceinline__ void red4(float* p, float4 v) {
    asm volatile("red.global.add.v4.f32 [%0], {%1,%2,%3,%4};"
                 :: "l"(p), "f"(v.x), "f"(v.y), "f"(v.z), "f"(v.w) : "memory");
}
__device__ __forceinline__ void red2(float* p, float2 v) {
    asm volatile("red.global.add.v2.f32 [%0], {%1,%2};"
                 :: "l"(p), "f"(v.x), "f"(v.y) : "memory");
}

// ---- edge scatter layer 1: tmp1[dst] += g1[src], 4 threads/edge ----
__global__ void edge1_kernel(const int* __restrict__ src,
                             const int* __restrict__ dst, int e) {
    int t = blockIdx.x * blockDim.x + threadIdx.x;
    int ei = t >> 2;
    if (ei >= e) return;
    int q = (t & 3) << 2;
    int s = src[ei], d = dst[ei];
    float4 v = *(const float4*)(g_g1 + s * HID + q);
    red4(g_tmp1 + d * HID + q, v);
}

// ---- finalize layer1 + GEMM2 fused: h=relu(dinv*(tmp1+g1)+b1); g2=(h@W2)*dinv ----
__global__ __launch_bounds__(256) void fin1_kernel(const float* __restrict__ b1,
                                                   const float* __restrict__ W2,
                                                   int n) {
    __shared__ float w2s[HID * NC];
    __shared__ float b1s[HID];
    int tid = threadIdx.x;
    if (tid < HID * NC) w2s[tid] = W2[tid];
    if (tid < HID)      b1s[tid] = b1[tid];
    __syncthreads();

    int i = blockIdx.x * 256 + tid;
    if (i >= n) return;
    float dv = g_dinv[i];

    float h[16];
    const float4* tp = (const float4*)(g_tmp1 + i * HID);
    const float4* gp = (const float4*)(g_g1 + i * HID);
#pragma unroll
    for (int o4 = 0; o4 < 4; ++o4) {
        float4 t = tp[o4], g = gp[o4];
        h[o4 * 4 + 0] = fmaxf(fmaf(dv, t.x + g.x, b1s[o4 * 4 + 0]), 0.f);
        h[o4 * 4 + 1] = fmaxf(fmaf(dv, t.y + g.y, b1s[o4 * 4 + 1]), 0.f);
        h[o4 * 4 + 2] = fmaxf(fmaf(dv, t.z + g.z, b1s[o4 * 4 + 2]), 0.f);
        h[o4 * 4 + 3] = fmaxf(fmaf(dv, t.w + g.w, b1s[o4 * 4 + 3]), 0.f);
    }

    float acc[NC];
#pragma unroll
    for (int c = 0; c < NC; ++c) acc[c] = 0.f;
#pragma unroll
    for (int o = 0; o < HID; ++o) {
        float hv = h[o];
#pragma unroll
        for (int c = 0; c < NC; ++c) acc[c] = fmaf(hv, w2s[o * NC + c], acc[c]);
    }

    float* out = g_g2 + i * CP;
    ((float4*)out)[0] = make_float4(acc[0] * dv, acc[1] * dv, acc[2] * dv, acc[3] * dv);
    ((float4*)out)[1] = make_float4(acc[4] * dv, acc[5] * dv, acc[6] * dv, acc[7] * dv);
    ((float4*)out)[2] = make_float4(acc[8] * dv, acc[9] * dv, 0.f, 0.f);
}

// ---- edge scatter layer 2: tmp2[dst] += g2[src] (10 real cols):
// 3 threads/edge: r=0,1 -> red4 on cols 0-7; r=2 -> red2 on cols 8-9 ----
__global__ void edge2_kernel(const int* __restrict__ src,
                             const int* __restrict__ dst, int e) {
    int t = blockIdx.x * blockDim.x + threadIdx.x;
    int ei = t / 3;
    if (ei >= e) return;
    int r = t - ei * 3;
    int s = src[ei], d = dst[ei];
    if (r < 2) {
        int q = r << 2;
        float4 v = *(const float4*)(g_g2 + s * CP + q);
        red4(g_tmp2 + d * CP + q, v);
    } else {
        float2 v = *(const float2*)(g_g2 + s * CP + 8);
        red2(g_tmp2 + d * CP + 8, v);
    }
}

// ---- finalize layer2 + softmax ----
__global__ __launch_bounds__(256) void fin2_kernel(const float* __restrict__ b2,
                                                   float* __restrict__ out, int n) {
    __shared__ float b2s[NC];
    if (threadIdx.x < NC) b2s[threadIdx.x] = b2[threadIdx.x];
    __syncthreads();
    int i = blockIdx.x * blockDim.x + threadIdx.x;
    if (i >= n) return;
    float dv = g_dinv[i];
    const float* tp = g_tmp2 + i * CP;
    const float* gp = g_g2 + i * CP;
    float l[NC];
    float m = -1e30f;
#pragma unroll
    for (int c = 0; c < NC; ++c) {
        l[c] = fmaf(dv, tp[c] + gp[c], b2s[c]);
        m = fmaxf(m, l[c]);
    }
    float sum = 0.f;
#pragma unroll
    for (int c = 0; c < NC; ++c) {
        l[c] = expf(l[c] - m);
        sum += l[c];
    }
    float inv = 1.0f / sum;
#pragma unroll
    for (int c = 0; c < NC; ++c) out[i * NC + c] = l[c] * inv;
}

// ---------------------------------------------------------------
extern "C" void kernel_launch(void* const* d_in, const int* in_sizes, int n_in,
                              void* d_out, int out_size) {
    const float* x  = (const float*)d_in[0];
    const int*   ei = (const int*)  d_in[1];
    const float* W1 = (const float*)d_in[2];
    const float* b1 = (const float*)d_in[3];
    const float* W2 = (const float*)d_in[4];
    const float* b2 = (const float*)d_in[5];
    float* out = (float*)d_out;

    int n = in_sizes[0] / F_IN;
    int e = in_sizes[1] / 2;
    const int* src = ei;
    const int* dst = ei + e;

    int zt = n * (HID / 4 + CP / 4) + (n + 3) / 4;
    zero_kernel<<<(zt + 255) / 256, 256>>>(n);
    deg_kernel <<<(e + 255) / 256, 256>>>(dst, e);
    dinv_kernel<<<(n + 255) / 256, 256>>>(n);
    gemm1_kernel<<<(n + 255) / 256, 256>>>(x, W1, n);
    edge1_kernel<<<(4 * e + 255) / 256, 256>>>(src, dst, e);
    fin1_kernel<<<(n + 255) / 256, 256>>>(b1, W2, n);
    edge2_kernel<<<(3 * e + 255) / 256, 256>>>(src, dst, e);
    fin2_kernel<<<(n + 255) / 256, 256>>>(b2, out, n);
}

// round 9
// speedup vs baseline: 1.1844x; 1.0598x over previous
#include <cuda_runtime.h>
#include <math.h>

#define NMAX 100000
#define EMAX 3200000
#define F_IN 128
#define HID  16
#define NC   10
#define CP   16   // layer-2 width padded to 16 so both layers share gather16

// ---- scratch (static device globals; no allocation allowed) ----
__device__ float g_g1  [NMAX * HID];  // (x@W1) * dinv[src-side]
__device__ float g_tmp1[NMAX * HID];  // gathered sums layer 1
__device__ float g_g2  [NMAX * CP];   // (h@W2) * dinv, padded to 16
__device__ float g_tmp2[NMAX * CP];   // gathered sums layer 2
__device__ float g_dinv[NMAX];
__device__ int   g_cnt [NMAX];        // in-degree (dst counts)
__device__ int   g_cnt2[NMAX];        // placement cursors
__device__ int   g_base[NMAX];        // CSR row offsets (by dst)
__device__ int   g_bsum[512];         // block sums for scan
__device__ int   g_boff[512];         // scanned block offsets
__device__ int   g_csr [EMAX];        // src indices grouped by dst

// ---------------------------------------------------------------
__global__ void zero_kernel(int n) {
    int i = blockIdx.x * blockDim.x + threadIdx.x;
    if (i < n) { g_cnt[i] = 0; g_cnt2[i] = 0; }
}

__global__ void deg_kernel(const int* __restrict__ dst, int e) {
    int i = blockIdx.x * blockDim.x + threadIdx.x;
    if (i < e) atomicAdd(&g_cnt[dst[i]], 1);
}

__global__ void dinv_kernel(int n) {
    int i = blockIdx.x * blockDim.x + threadIdx.x;
    if (i < n) g_dinv[i] = rsqrtf((float)g_cnt[i] + 1.0f);
}

// ---- scan stage 1: per-block sums of g_cnt ----
__global__ __launch_bounds__(256) void scan1_kernel(int n) {
    __shared__ int wsum[8];
    int i = blockIdx.x * 256 + threadIdx.x;
    int lane = threadIdx.x & 31, warp = threadIdx.x >> 5;
    int v = (i < n) ? g_cnt[i] : 0;
#pragma unroll
    for (int d = 16; d > 0; d >>= 1) v += __shfl_down_sync(~0u, v, d);
    if (lane == 0) wsum[warp] = v;
    __syncthreads();
    if (threadIdx.x == 0) {
        int s = 0;
#pragma unroll
        for (int w = 0; w < 8; ++w) s += wsum[w];
        g_bsum[blockIdx.x] = s;
    }
}

// ---- scan stage 2: exclusive scan of block sums (nb <= 512), 1 block ----
__global__ __launch_bounds__(512) void scan2_kernel(int nb) {
    __shared__ int sm[512];
    int t = threadIdx.x;
    sm[t] = (t < nb) ? g_bsum[t] : 0;
    __syncthreads();
    for (int d = 1; d < 512; d <<= 1) {
        int add = (t >= d) ? sm[t - d] : 0;
        __syncthreads();
        sm[t] += add;
        __syncthreads();
    }
    if (t < nb) g_boff[t] = (t == 0) ? 0 : sm[t - 1];
}

// ---- scan stage 3: intra-block exclusive scan + block offset -> g_base ----
__global__ __launch_bounds__(256) void scan3_kernel(int n) {
    __shared__ int wsum[8];
    int i = blockIdx.x * 256 + threadIdx.x;
    int lane = threadIdx.x & 31, warp = threadIdx.x >> 5;
    int orig = (i < n) ? g_cnt[i] : 0;
    int v = orig;
#pragma unroll
    for (int d = 1; d < 32; d <<= 1) {
        int t = __shfl_up_sync(~0u, v, d);
        if (lane >= d) v += t;
    }
    if (lane == 31) wsum[warp] = v;
    __syncthreads();
    if (warp == 0 && lane < 8) {
        int s = wsum[lane];
#pragma unroll
        for (int d = 1; d < 8; d <<= 1) {
            int t = __shfl_up_sync(0xffu, s, d);
            if (lane >= d) s += t;
        }
        wsum[lane] = s;
    }
    __syncthreads();
    int wbase = (warp > 0) ? wsum[warp - 1] : 0;
    if (i < n) g_base[i] = g_boff[blockIdx.x] + wbase + v - orig;
}

// ---- CSR placement: group src indices by dst ----
__global__ void place_kernel(const int* __restrict__ src,
                             const int* __restrict__ dst, int e) {
    int i = blockIdx.x * blockDim.x + threadIdx.x;
    if (i >= e) return;
    int d = dst[i];
    int pos = g_base[d] + atomicAdd(&g_cnt2[d], 1);
    g_csr[pos] = src[i];
}

// ---- GEMM1: g1 = (x @ W1) * dinv (warp-staged) ----
__global__ __launch_bounds__(256) void gemm1_kernel(const float* __restrict__ x,
                                                    const float* __restrict__ W1,
                                                    int n) {
    __shared__ float w1s[F_IN * HID];
    __shared__ float xs[8][32][33];
#pragma unroll
    for (int i = threadIdx.x; i < F_IN * HID; i += 256)
        w1s[i] = W1[i];
    __syncthreads();

    const int warp = threadIdx.x >> 5;
    const int lane = threadIdx.x & 31;
    const int row0 = blockIdx.x * 256 + warp * 32;
    const int myrow = row0 + lane;

    float acc[16];
#pragma unroll
    for (int o = 0; o < 16; ++o) acc[o] = 0.f;

#pragma unroll 1
    for (int kc = 0; kc < 4; ++kc) {
#pragma unroll 8
        for (int r = 0; r < 32; ++r) {
            int row = row0 + r;
            xs[warp][r][lane] = (row < n)
                ? x[(size_t)row * F_IN + kc * 32 + lane] : 0.f;
        }
        __syncwarp();
#pragma unroll
        for (int k = 0; k < 32; ++k) {
            float xv = xs[warp][lane][k];
            const float* w = w1s + (kc * 32 + k) * HID;
            float4 wa = *(const float4*)(w + 0);
            float4 wb = *(const float4*)(w + 4);
            float4 wc = *(const float4*)(w + 8);
            float4 wd = *(const float4*)(w + 12);
            acc[0]  = fmaf(xv, wa.x, acc[0]);  acc[1]  = fmaf(xv, wa.y, acc[1]);
            acc[2]  = fmaf(xv, wa.z, acc[2]);  acc[3]  = fmaf(xv, wa.w, acc[3]);
            acc[4]  = fmaf(xv, wb.x, acc[4]);  acc[5]  = fmaf(xv, wb.y, acc[5]);
            acc[6]  = fmaf(xv, wb.z, acc[6]);  acc[7]  = fmaf(xv, wb.w, acc[7]);
            acc[8]  = fmaf(xv, wc.x, acc[8]);  acc[9]  = fmaf(xv, wc.y, acc[9]);
            acc[10] = fmaf(xv, wc.z, acc[10]); acc[11] = fmaf(xv, wc.w, acc[11]);
            acc[12] = fmaf(xv, wd.x, acc[12]); acc[13] = fmaf(xv, wd.y, acc[13]);
            acc[14] = fmaf(xv, wd.z, acc[14]); acc[15] = fmaf(xv, wd.w, acc[15]);
        }
        __syncwarp();
    }

    if (myrow < n) {
        float dv = g_dinv[myrow];
        float* out = g_g1 + (size_t)myrow * HID;
#pragma unroll
        for (int o = 0; o < 16; o += 4)
            *(float4*)(out + o) = make_float4(acc[o] * dv, acc[o + 1] * dv,
                                              acc[o + 2] * dv, acc[o + 3] * dv);
    }
}

// ---- gather: out[v] = sum over incoming edges of in[src], 16 floats wide.
// One warp per node; 4 lanes per edge (quarter q), 8 edges per iteration;
// xor-butterfly over strides 4/8/16 reduces edge slots; lanes 0-3 write.
// LAYER selects the device-global in/out arrays INSIDE device code (a
// __device__ symbol must never be passed from host). ----
template <int LAYER>
__global__ __launch_bounds__(256) void gather16_kernel(int n) {
    const float* __restrict__ in = (LAYER == 0) ? g_g1 : g_g2;
    float* __restrict__ out      = (LAYER == 0) ? g_tmp1 : g_tmp2;

    int gw = (blockIdx.x * 256 + threadIdx.x) >> 5;
    if (gw >= n) return;
    int lane = threadIdx.x & 31;
    int eq = lane >> 2, q = lane & 3;
    int start = g_base[gw];
    int m = g_cnt[gw];
    const int* cs = g_csr + start;

    float4 acc = make_float4(0.f, 0.f, 0.f, 0.f);
    int j = eq;
    for (; j + 8 < m; j += 16) {
        int s0 = cs[j], s1 = cs[j + 8];
        float4 a = *(const float4*)(in + (size_t)s0 * 16 + q * 4);
        float4 b = *(const float4*)(in + (size_t)s1 * 16 + q * 4);
        acc.x += a.x + b.x; acc.y += a.y + b.y;
        acc.z += a.z + b.z; acc.w += a.w + b.w;
    }
    for (; j < m; j += 8) {
        int s = cs[j];
        float4 a = *(const float4*)(in + (size_t)s * 16 + q * 4);
        acc.x += a.x; acc.y += a.y; acc.z += a.z; acc.w += a.w;
    }
#pragma unroll
    for (int st = 4; st < 32; st <<= 1) {
        acc.x += __shfl_xor_sync(~0u, acc.x, st);
        acc.y += __shfl_xor_sync(~0u, acc.y, st);
        acc.z += __shfl_xor_sync(~0u, acc.z, st);
        acc.w += __shfl_xor_sync(~0u, acc.w, st);
    }
    if (lane < 4)
        *(float4*)(out + (size_t)gw * 16 + q * 4) = acc;
}

// ---- finalize layer1 + GEMM2: h=relu(dinv*(tmp1+g1)+b1); g2=(h@W2)*dinv ----
__global__ __launch_bounds__(256) void fin1_kernel(const float* __restrict__ b1,
                                                   const float* __restrict__ W2,
                                                   int n) {
    __shared__ float w2s[HID * NC];
    __shared__ float b1s[HID];
    int tid = threadIdx.x;
    if (tid < HID * NC) w2s[tid] = W2[tid];
    if (tid < HID)      b1s[tid] = b1[tid];
    __syncthreads();

    int i = blockIdx.x * 256 + tid;
    if (i >= n) return;
    float dv = g_dinv[i];

    float h[16];
    const float4* tp = (const float4*)(g_tmp1 + (size_t)i * HID);
    const float4* gp = (const float4*)(g_g1 + (size_t)i * HID);
#pragma unroll
    for (int o4 = 0; o4 < 4; ++o4) {
        float4 t = tp[o4], g = gp[o4];
        h[o4 * 4 + 0] = fmaxf(fmaf(dv, t.x + g.x, b1s[o4 * 4 + 0]), 0.f);
        h[o4 * 4 + 1] = fmaxf(fmaf(dv, t.y + g.y, b1s[o4 * 4 + 1]), 0.f);
        h[o4 * 4 + 2] = fmaxf(fmaf(dv, t.z + g.z, b1s[o4 * 4 + 2]), 0.f);
        h[o4 * 4 + 3] = fmaxf(fmaf(dv, t.w + g.w, b1s[o4 * 4 + 3]), 0.f);
    }

    float acc[NC];
#pragma unroll
    for (int c = 0; c < NC; ++c) acc[c] = 0.f;
#pragma unroll
    for (int o = 0; o < HID; ++o) {
        float hv = h[o];
#pragma unroll
        for (int c = 0; c < NC; ++c) acc[c] = fmaf(hv, w2s[o * NC + c], acc[c]);
    }

    float* out = g_g2 + (size_t)i * CP;
    ((float4*)out)[0] = make_float4(acc[0] * dv, acc[1] * dv, acc[2] * dv, acc[3] * dv);
    ((float4*)out)[1] = make_float4(acc[4] * dv, acc[5] * dv, acc[6] * dv, acc[7] * dv);
    ((float4*)out)[2] = make_float4(acc[8] * dv, acc[9] * dv, 0.f, 0.f);
    ((float4*)out)[3] = make_float4(0.f, 0.f, 0.f, 0.f);
}

// ---- finalize layer2 + softmax ----
__global__ __launch_bounds__(256) void fin2_kernel(const float* __restrict__ b2,
                                                   float* __restrict__ out, int n) {
    __shared__ float b2s[NC];
    if (threadIdx.x < NC) b2s[threadIdx.x] = b2[threadIdx.x];
    __syncthreads();
    int i = blockIdx.x * blockDim.x + threadIdx.x;
    if (i >= n) return;
    float dv = g_dinv[i];
    const float* tp = g_tmp2 + (size_t)i * CP;
    const float* gp = g_g2 + (size_t)i * CP;
    float l[NC];
    float m = -1e30f;
#pragma unroll
    for (int c = 0; c < NC; ++c) {
        l[c] = fmaf(dv, tp[c] + gp[c], b2s[c]);
        m = fmaxf(m, l[c]);
    }
    float sum = 0.f;
#pragma unroll
    for (int c = 0; c < NC; ++c) {
        l[c] = expf(l[c] - m);
        sum += l[c];
    }
    float inv = 1.0f / sum;
#pragma unroll
    for (int c = 0; c < NC; ++c) out[i * NC + c] = l[c] * inv;
}

// ---------------------------------------------------------------
extern "C" void kernel_launch(void* const* d_in, const int* in_sizes, int n_in,
                              void* d_out, int out_size) {
    const float* x  = (const float*)d_in[0];
    const int*   ei = (const int*)  d_in[1];
    const float* W1 = (const float*)d_in[2];
    const float* b1 = (const float*)d_in[3];
    const float* W2 = (const float*)d_in[4];
    const float* b2 = (const float*)d_in[5];
    float* out = (float*)d_out;

    int n = in_sizes[0] / F_IN;
    int e = in_sizes[1] / 2;
    const int* src = ei;
    const int* dst = ei + e;
    int nb = (n + 255) / 256;   // blocks for node-wise kernels (<=512 for scan2)

    zero_kernel <<<nb, 256>>>(n);
    deg_kernel  <<<(e + 255) / 256, 256>>>(dst, e);
    dinv_kernel <<<nb, 256>>>(n);
    scan1_kernel<<<nb, 256>>>(n);
    scan2_kernel<<<1, 512>>>(nb);
    scan3_kernel<<<nb, 256>>>(n);
    place_kernel<<<(e + 255) / 256, 256>>>(src, dst, e);
    gemm1_kernel<<<nb, 256>>>(x, W1, n);
    gather16_kernel<0><<<(n * 32 + 255) / 256, 256>>>(n);
    fin1_kernel <<<nb, 256>>>(b1, W2, n);
    gather16_kernel<1><<<(n * 32 + 255) / 256, 256>>>(n);
    fin2_kernel <<<nb, 256>>>(b2, out, n);
}